// round 15
// baseline (speedup 1.0000x reference)
#include <cuda_runtime.h>
#include <cuda_bf16.h>
#include <cstdint>
#include <math.h>

// ---------------- problem constants ----------------
#define Hd   256
#define NHd  4
#define HDd  64
#define BAT  8
#define SQI  2048
#define SQT  1024
#define RI   (BAT*SQI)
#define RT   (BAT*SQT)
#define NZ   (BAT*NHd)       // 32

// ---------------- scratch ----------------
__device__ float g_im[(size_t)RI*Hd];
__device__ float g_tx[(size_t)RT*Hd];
__device__ float g_w[8*(size_t)Hd*Hd];
__device__ float g_qi[(size_t)RI*Hd];
__device__ float g_ki[(size_t)RI*Hd];
__device__ float g_vi[(size_t)RI*Hd];   // packed, TRANSPOSED [z][64][SQI]
__device__ float g_qt[(size_t)RT*Hd];
__device__ float g_kt[(size_t)RT*Hd];
__device__ float g_vt[(size_t)RT*Hd];   // packed, TRANSPOSED [z][64][SQT]
__device__ float g_ai[(size_t)RI*Hd];
__device__ float g_at[(size_t)RT*Hd];
__device__ float g_oi[(size_t)RI*Hd];
__device__ float g_ot[(size_t)RT*Hd];
__device__ float g_S0[(size_t)NZ*SQI*SQT]; // i2t packed w (for A output)
__device__ float g_S1[(size_t)NZ*SQT*SQI]; // t2i packed w
__device__ float g_rsum[NZ*SQI + NZ*SQT];

// ================= helpers =================
__device__ __forceinline__ uint32_t smem_to_u32(const void* p) {
    uint32_t a;
    asm("{ .reg .u64 t; cvta.to.shared.u64 t, %1; cvt.u32.u64 %0, t; }" : "=r"(a) : "l"(p));
    return a;
}
__device__ __forceinline__ void ldm_x4(uint32_t r[4], uint32_t addr) {
    asm volatile("ldmatrix.sync.aligned.m8n8.x4.shared.b16 {%0,%1,%2,%3}, [%4];"
        : "=r"(r[0]), "=r"(r[1]), "=r"(r[2]), "=r"(r[3]) : "r"(addr));
}
__device__ __forceinline__ void mma_bf16(float c[4], const uint32_t a[4],
                                         uint32_t b0, uint32_t b1) {
    asm volatile(
        "mma.sync.aligned.m16n8k16.row.col.f32.bf16.bf16.f32 "
        "{%0,%1,%2,%3}, {%4,%5,%6,%7}, {%8,%9}, {%0,%1,%2,%3};"
        : "+f"(c[0]), "+f"(c[1]), "+f"(c[2]), "+f"(c[3])
        : "r"(a[0]), "r"(a[1]), "r"(a[2]), "r"(a[3]), "r"(b0), "r"(b1));
}
__device__ __forceinline__ uint32_t pack_f32(float x) {
    __nv_bfloat16 hb = __float2bfloat16(x);
    float hf = __bfloat162float(hb);
    __nv_bfloat16 lb = __float2bfloat16(x - hf);
    return ((uint32_t)__bfloat16_as_ushort(hb) << 16) | (uint32_t)__bfloat16_as_ushort(lb);
}
__device__ __forceinline__ float unpack_f32(uint32_t u) {
    return __bfloat162float(__ushort_as_bfloat16((unsigned short)(u >> 16)))
         + __bfloat162float(__ushort_as_bfloat16((unsigned short)(u & 0xffff)));
}
// two fp32 -> bf16x2 hi plane + bf16x2 lo(residual) plane; low half = first elem
__device__ __forceinline__ void split2(float a, float b, uint32_t& h, uint32_t& l) {
    __nv_bfloat16 ah = __float2bfloat16(a), bh = __float2bfloat16(b);
    __nv_bfloat16 al = __float2bfloat16(a - __bfloat162float(ah));
    __nv_bfloat16 bl = __float2bfloat16(b - __bfloat162float(bh));
    h = ((uint32_t)__bfloat16_as_ushort(bh) << 16) | (uint32_t)__bfloat16_as_ushort(ah);
    l = ((uint32_t)__bfloat16_as_ushort(bl) << 16) | (uint32_t)__bfloat16_as_ushort(al);
}

// ---------------- GEMM smem layout (projections) ----------------
#define RSTR 56
#define OFF_AL 14336
#define OFF_BH 28672
#define OFF_BL 35840
#define STG_BYTES 43008
#define SMEM_GEMM (2*STG_BYTES)

struct GArgs {
    const uint32_t* A; int lda;
    const uint32_t* B; int ldb;
    const float* bias;
    void* C; int ldc;
    int K; float alpha;
    int m0, n0;
    int tr_ld, tr_rows, tr_col0;
    const float* rs;
};

__device__ __forceinline__ void sts8(uint16_t* hi, uint16_t* lo, int idx, uint4 a, uint4 b) {
    uint4 H, L;
    H.x = __byte_perm(a.x, a.y, 0x7632); H.y = __byte_perm(a.z, a.w, 0x7632);
    H.z = __byte_perm(b.x, b.y, 0x7632); H.w = __byte_perm(b.z, b.w, 0x7632);
    L.x = __byte_perm(a.x, a.y, 0x5410); L.y = __byte_perm(a.z, a.w, 0x5410);
    L.z = __byte_perm(b.x, b.y, 0x5410); L.w = __byte_perm(b.z, b.w, 0x5410);
    *(uint4*)(hi + idx) = H;
    *(uint4*)(lo + idx) = L;
}

// OMODE: 0 fp32 row-major, 1 packed row-major (opt rowsum scale), 2 packed transposed
template <int OMODE, bool BIAS>
__device__ void gemm_mma(GArgs g) {
    extern __shared__ char smem[];
    const uint32_t sbase = smem_to_u32(smem);
    const int tid = threadIdx.x;
    const int lane = tid & 31, wid = tid >> 5;
    const int warpM = wid >> 1, warpN = wid & 1;

    float c[2][4][4];
#pragma unroll
    for (int i = 0; i < 2; i++)
#pragma unroll
        for (int j = 0; j < 4; j++)
#pragma unroll
            for (int q = 0; q < 4; q++) c[i][j][q] = 0.f;

    const int S = g.K >> 5;
    const int arow = tid >> 1, ak0 = (tid & 1) * 16;
    const int brow = tid >> 2, bk0 = (tid & 3) * 8;
    uint4 areg[4], breg[2];

#define LOADR(s) do { \
        const uint32_t* Ap = g.A + (size_t)(g.m0 + arow) * g.lda + (s) * 32 + ak0; \
        _Pragma("unroll") for (int j = 0; j < 4; j++) areg[j] = *(const uint4*)(Ap + j * 4); \
        const uint32_t* Bp = g.B + (size_t)(g.n0 + brow) * g.ldb + (s) * 32 + bk0; \
        _Pragma("unroll") for (int j = 0; j < 2; j++) breg[j] = *(const uint4*)(Bp + j * 4); \
    } while (0)

#define STS(buf) do { \
        char* p = smem + (buf) * STG_BYTES; \
        uint16_t* Ah = (uint16_t*)p;               uint16_t* Al = (uint16_t*)(p + OFF_AL); \
        uint16_t* Bh = (uint16_t*)(p + OFF_BH);    uint16_t* Bl = (uint16_t*)(p + OFF_BL); \
        sts8(Ah, Al, arow * RSTR + ak0,     areg[0], areg[1]); \
        sts8(Ah, Al, arow * RSTR + ak0 + 8, areg[2], areg[3]); \
        sts8(Bh, Bl, brow * RSTR + bk0,     breg[0], breg[1]); \
    } while (0)

    const int sel = lane >> 3, r8 = lane & 7;
    const int rloc = (sel & 1) * 8 + r8;
    const int cloc = (sel >> 1) * 8;

#define COMPUTE(buf) do { \
        uint32_t AhB = sbase + (buf) * STG_BYTES, AlB = AhB + OFF_AL; \
        uint32_t BhB = AhB + OFF_BH,              BlB = AhB + OFF_BL; \
        _Pragma("unroll") for (int kh = 0; kh < 2; kh++) { \
            uint32_t ah[2][4], al[2][4], bh[2][4], bl[2][4]; \
            _Pragma("unroll") for (int i = 0; i < 2; i++) { \
                uint32_t off = (uint32_t)(((warpM * 32 + i * 16 + rloc) * RSTR + kh * 16 + cloc) * 2); \
                ldm_x4(ah[i], AhB + off); ldm_x4(al[i], AlB + off); \
            } \
            _Pragma("unroll") for (int pp = 0; pp < 2; pp++) { \
                uint32_t off = (uint32_t)(((warpN * 32 + pp * 16 + rloc) * RSTR + kh * 16 + cloc) * 2); \
                ldm_x4(bh[pp], BhB + off); ldm_x4(bl[pp], BlB + off); \
            } \
            _Pragma("unroll") for (int i = 0; i < 2; i++) \
            _Pragma("unroll") for (int j = 0; j < 4; j++) { \
                const int pp = j >> 1, q = j & 1; \
                mma_bf16(c[i][j], ah[i], bh[pp][q], bh[pp][q + 2]); \
                mma_bf16(c[i][j], ah[i], bl[pp][q], bl[pp][q + 2]); \
                mma_bf16(c[i][j], al[i], bh[pp][q], bh[pp][q + 2]); \
            } \
        } \
    } while (0)

    LOADR(0); STS(0);
    __syncthreads();
    for (int s = 0; s < S; ++s) {
        if (s + 1 < S) LOADR(s + 1);
        COMPUTE(s & 1);
        if (s + 1 < S) STS((s + 1) & 1);
        __syncthreads();
    }

    const int gq = lane >> 2, tig = lane & 3;
#pragma unroll
    for (int i = 0; i < 2; i++) {
        const int r0 = g.m0 + warpM * 32 + i * 16 + gq;
        float inv0 = 1.f, inv1 = 1.f;
        if (OMODE == 1) {
            if (g.rs) { inv0 = 1.f / g.rs[r0]; inv1 = 1.f / g.rs[r0 + 8]; }
        }
#pragma unroll
        for (int j = 0; j < 4; j++) {
            const int nc = warpN * 32 + j * 8 + tig * 2;
            float v00 = c[i][j][0] * g.alpha, v01 = c[i][j][1] * g.alpha;
            float v10 = c[i][j][2] * g.alpha, v11 = c[i][j][3] * g.alpha;
            if (BIAS) {
                float b0 = g.bias[g.n0 + nc], b1 = g.bias[g.n0 + nc + 1];
                v00 += b0; v01 += b1; v10 += b0; v11 += b1;
            }
            if (OMODE == 0) {
                float* Cf = (float*)g.C;
                *(float2*)(Cf + (size_t)r0 * g.ldc + g.n0 + nc)       = make_float2(v00, v01);
                *(float2*)(Cf + (size_t)(r0 + 8) * g.ldc + g.n0 + nc) = make_float2(v10, v11);
            } else if (OMODE == 1) {
                v00 *= inv0; v01 *= inv0; v10 *= inv1; v11 *= inv1;
                uint32_t* Cu = (uint32_t*)g.C;
                *(uint2*)(Cu + (size_t)r0 * g.ldc + g.n0 + nc)       = make_uint2(pack_f32(v00), pack_f32(v01));
                *(uint2*)(Cu + (size_t)(r0 + 8) * g.ldc + g.n0 + nc) = make_uint2(pack_f32(v10), pack_f32(v11));
            } else {
                uint32_t* Ct = (uint32_t*)g.C;
                const int bb0 = r0 / g.tr_rows, sr0 = r0 % g.tr_rows;
                const int bb1 = (r0 + 8) / g.tr_rows, sr1 = (r0 + 8) % g.tr_rows;
                const size_t base0 = (size_t)((bb0 * 4 + g.tr_col0) * 64 + nc) * g.tr_ld + sr0;
                const size_t base1 = (size_t)((bb1 * 4 + g.tr_col0) * 64 + nc) * g.tr_ld + sr1;
                Ct[base0]            = pack_f32(v00);
                Ct[base0 + g.tr_ld]  = pack_f32(v01);
                Ct[base1]            = pack_f32(v10);
                Ct[base1 + g.tr_ld]  = pack_f32(v11);
            }
        }
    }
#undef LOADR
#undef STS
#undef COMPUTE
}

// ---------------- fused attention kernel ----------------
// Block = 256 thr = 8 warps x 16 q-rows. Per (z, 128-row q-tile): loop 64-wide kv
// tiles: S = 2*Q.K (MMA), w = exp(S) -> store packed w to S-global, accumulate
// rowsums in regs, P-frags from C-frags (register identity), O += P.V (MMA).
// End: O *= 1/rs (packed out), write rs.
#define DSTR 72                          // smem row stride in halves (144B)
#define ATT_SQH 0
#define ATT_SQL 18432
#define ATT_BUF 36864                    // per-buffer: K hi,lo + V hi,lo
#define ATT_KH  0
#define ATT_KL  9216
#define ATT_VH  18432
#define ATT_VL  27648
#define ATT_BUFSZ 36864
#define SMEM_ATT (ATT_BUF + 2*ATT_BUFSZ) // 110592

__global__ void __launch_bounds__(256) k_attn_all(
    const uint32_t* qi, const uint32_t* kt, const uint32_t* qt, const uint32_t* ki,
    const uint32_t* vt, const uint32_t* vi,
    uint32_t* S0, uint32_t* S1, float* rsum,
    uint32_t* ai, uint32_t* at)
{
    extern __shared__ char smem[];
    const uint32_t sb = smem_to_u32(smem);
    const int tid = threadIdx.x;
    const int lane = tid & 31, wid = tid >> 5;
    const int z = blockIdx.y, b = z >> 2, h = z & 3;
    const int x = blockIdx.x;

    const uint32_t *Q, *Km, *V;
    uint32_t *Sg, *O;
    float* rsg;
    int m0, Skv;
    if (x < 8) {          // t2i (longer blocks first)
        Q = qt + (size_t)b * SQT * Hd + h * HDd;
        Km = ki + (size_t)b * SQI * Hd + h * HDd;
        V = vi + (size_t)z * HDd * SQI;
        Sg = S1 + (size_t)z * SQT * SQI;
        O = at + (size_t)b * SQT * Hd + h * HDd;
        rsg = rsum + NZ * SQI + (size_t)z * SQT;
        m0 = x * 128; Skv = SQI;
    } else {              // i2t
        Q = qi + (size_t)b * SQI * Hd + h * HDd;
        Km = kt + (size_t)b * SQT * Hd + h * HDd;
        V = vt + (size_t)z * HDd * SQT;
        Sg = S0 + (size_t)z * SQI * SQT;
        O = ai + (size_t)b * SQI * Hd + h * HDd;
        rsg = rsum + (size_t)z * SQI;
        m0 = (x - 8) * 128; Skv = SQT;
    }
    const int nsteps = Skv >> 6;

    // ---- stage Q (once) ----
    {
        const int qrow = tid >> 1, qoff = (tid & 1) * 32;
        const uint32_t* Qp = Q + (size_t)(m0 + qrow) * Hd + qoff;
        uint4 qv[8];
#pragma unroll
        for (int j = 0; j < 8; j++) qv[j] = *(const uint4*)(Qp + 4 * j);
        uint16_t* Qh = (uint16_t*)(smem + ATT_SQH);
        uint16_t* Ql = (uint16_t*)(smem + ATT_SQL);
#pragma unroll
        for (int j = 0; j < 4; j++)
            sts8(Qh, Ql, qrow * DSTR + qoff + 8 * j, qv[2 * j], qv[2 * j + 1]);
    }

    // ---- K/V staging helpers ----
    const int krow = tid >> 2, koff = (tid & 3) * 16;
    uint4 kreg[4], vreg[4];
#define ATT_LOAD(s) do { \
        const uint32_t* Kp = Km + (size_t)((s) * 64 + krow) * Hd + koff; \
        _Pragma("unroll") for (int j = 0; j < 4; j++) kreg[j] = *(const uint4*)(Kp + 4 * j); \
        const uint32_t* Vp = V + (size_t)krow * Skv + (s) * 64 + koff; \
        _Pragma("unroll") for (int j = 0; j < 4; j++) vreg[j] = *(const uint4*)(Vp + 4 * j); \
    } while (0)
#define ATT_STS(buf) do { \
        char* p = smem + ATT_BUF + (buf) * ATT_BUFSZ; \
        sts8((uint16_t*)(p + ATT_KH), (uint16_t*)(p + ATT_KL), krow * DSTR + koff,     kreg[0], kreg[1]); \
        sts8((uint16_t*)(p + ATT_KH), (uint16_t*)(p + ATT_KL), krow * DSTR + koff + 8, kreg[2], kreg[3]); \
        sts8((uint16_t*)(p + ATT_VH), (uint16_t*)(p + ATT_VL), krow * DSTR + koff,     vreg[0], vreg[1]); \
        sts8((uint16_t*)(p + ATT_VH), (uint16_t*)(p + ATT_VL), krow * DSTR + koff + 8, vreg[2], vreg[3]); \
    } while (0)

    const int sel = lane >> 3, r8 = lane & 7;
    const int rloc = (sel & 1) * 8 + r8;
    const int cloc = (sel >> 1) * 8;
    const int g = lane >> 2, qd = lane & 3;

    float o[8][4];
#pragma unroll
    for (int nt = 0; nt < 8; nt++)
#pragma unroll
        for (int e = 0; e < 4; e++) o[nt][e] = 0.f;
    float rs0 = 0.f, rs1 = 0.f;

    ATT_LOAD(0); ATT_STS(0);
    __syncthreads();

    for (int s = 0; s < nsteps; ++s) {
        const int buf = s & 1;
        if (s + 1 < nsteps) ATT_LOAD(s + 1);

        const uint32_t bufb = sb + ATT_BUF + buf * ATT_BUFSZ;
        // ---- S tile = Q.K^T (K=64 -> 4 k-frags) ----
        float c[8][4];
#pragma unroll
        for (int nt = 0; nt < 8; nt++)
#pragma unroll
            for (int e = 0; e < 4; e++) c[nt][e] = 0.f;
#pragma unroll
        for (int kf = 0; kf < 4; kf++) {
            uint32_t qh[4], ql[4];
            const uint32_t qoffs = (uint32_t)(((16 * wid + rloc) * DSTR + kf * 16 + cloc) * 2);
            ldm_x4(qh, sb + ATT_SQH + qoffs);
            ldm_x4(ql, sb + ATT_SQL + qoffs);
#pragma unroll
            for (int pp = 0; pp < 4; pp++) {
                uint32_t kh[4], kl[4];
                const uint32_t koffs = (uint32_t)(((pp * 16 + rloc) * DSTR + kf * 16 + cloc) * 2);
                ldm_x4(kh, bufb + ATT_KH + koffs);
                ldm_x4(kl, bufb + ATT_KL + koffs);
#pragma unroll
                for (int q = 0; q < 2; q++) {
                    const int nt = pp * 2 + q;
                    mma_bf16(c[nt], qh, kh[q], kh[q + 2]);
                    mma_bf16(c[nt], qh, kl[q], kl[q + 2]);
                    mma_bf16(c[nt], ql, kh[q], kh[q + 2]);
                }
            }
        }
        // ---- exp, store w, rowsum ----
        const int kv0 = s * 64;
        const int row0 = m0 + 16 * wid + g;
        float w[8][4];
#pragma unroll
        for (int nt = 0; nt < 8; nt++) {
            w[nt][0] = __expf(2.0f * c[nt][0]);
            w[nt][1] = __expf(2.0f * c[nt][1]);
            w[nt][2] = __expf(2.0f * c[nt][2]);
            w[nt][3] = __expf(2.0f * c[nt][3]);
            rs0 += w[nt][0] + w[nt][1];
            rs1 += w[nt][2] + w[nt][3];
            const int col = kv0 + nt * 8 + 2 * qd;
            *(uint2*)&Sg[(size_t)row0 * Skv + col] =
                make_uint2(pack_f32(w[nt][0]), pack_f32(w[nt][1]));
            *(uint2*)&Sg[(size_t)(row0 + 8) * Skv + col] =
                make_uint2(pack_f32(w[nt][2]), pack_f32(w[nt][3]));
        }
        // ---- P frags from C frags (register identity) ----
        uint32_t ph[4][4], pl[4][4];
#pragma unroll
        for (int kf = 0; kf < 4; kf++) {
            const int n0 = 2 * kf, n1 = n0 + 1;
            split2(w[n0][0], w[n0][1], ph[kf][0], pl[kf][0]);
            split2(w[n0][2], w[n0][3], ph[kf][1], pl[kf][1]);
            split2(w[n1][0], w[n1][1], ph[kf][2], pl[kf][2]);
            split2(w[n1][2], w[n1][3], ph[kf][3], pl[kf][3]);
        }
        // ---- O += P.V ----
#pragma unroll
        for (int kf = 0; kf < 4; kf++) {
#pragma unroll
            for (int pp = 0; pp < 4; pp++) {
                uint32_t vh[4], vl[4];
                const uint32_t voffs = (uint32_t)(((pp * 16 + rloc) * DSTR + kf * 16 + cloc) * 2);
                ldm_x4(vh, bufb + ATT_VH + voffs);
                ldm_x4(vl, bufb + ATT_VL + voffs);
#pragma unroll
                for (int q = 0; q < 2; q++) {
                    const int nt = pp * 2 + q;
                    mma_bf16(o[nt], ph[kf], vh[q], vh[q + 2]);
                    mma_bf16(o[nt], ph[kf], vl[q], vl[q + 2]);
                    mma_bf16(o[nt], pl[kf], vh[q], vh[q + 2]);
                }
            }
        }
        if (s + 1 < nsteps) ATT_STS((s + 1) & 1);
        __syncthreads();
    }

    // ---- epilogue: rowsums + normalized packed O ----
    rs0 += __shfl_xor_sync(0xffffffffu, rs0, 1);
    rs0 += __shfl_xor_sync(0xffffffffu, rs0, 2);
    rs1 += __shfl_xor_sync(0xffffffffu, rs1, 1);
    rs1 += __shfl_xor_sync(0xffffffffu, rs1, 2);
    const int row0 = m0 + 16 * wid + g;
    if (qd == 0) {
        rsg[row0] = rs0;
        rsg[row0 + 8] = rs1;
    }
    const float inv0 = 1.f / rs0, inv1 = 1.f / rs1;
#pragma unroll
    for (int nt = 0; nt < 8; nt++) {
        const int col = nt * 8 + 2 * qd;
        *(uint2*)&O[(size_t)row0 * Hd + col] =
            make_uint2(pack_f32(o[nt][0] * inv0), pack_f32(o[nt][1] * inv0));
        *(uint2*)&O[(size_t)(row0 + 8) * Hd + col] =
            make_uint2(pack_f32(o[nt][2] * inv1), pack_f32(o[nt][3] * inv1));
    }
#undef ATT_LOAD
#undef ATT_STS
}

// ---------------- other kernels ----------------
__global__ void __launch_bounds__(256) k_pack_all(
    const float* im, const float* tx,
    const float* w0, const float* w1, const float* w2, const float* w3,
    const float* w4, const float* w5, const float* w6, const float* w7,
    uint32_t* dim, uint32_t* dtx, uint32_t* dw)
{
    const int NIM = RI * Hd, NTX = RT * Hd, NW = Hd * Hd;
    int i = blockIdx.x * 256 + threadIdx.x;
    if (i >= NIM + NTX + 8 * NW) return;
    if (i < NIM) { dim[i] = pack_f32(im[i]); return; }
    i -= NIM;
    if (i < NTX) { dtx[i] = pack_f32(tx[i]); return; }
    i -= NTX;
    const int wsel = i / NW, wi = i % NW;
    const float* src;
    switch (wsel) {
        case 0: src = w0; break; case 1: src = w1; break;
        case 2: src = w2; break; case 3: src = w3; break;
        case 4: src = w4; break; case 5: src = w5; break;
        case 6: src = w6; break; default: src = w7; break;
    }
    dw[(size_t)wsel * NW + wi] = pack_f32(src[wi]);
}

__global__ void __launch_bounds__(256) k_proj_all(
    const uint32_t* im, const uint32_t* tx, const uint32_t* w,
    const float* i2t_bq, const float* i2t_bk, const float* i2t_bv,
    const float* t2i_bq, const float* t2i_bk, const float* t2i_bv,
    uint32_t* qi, uint32_t* ki, uint32_t* vi,
    uint32_t* qt, uint32_t* kt, uint32_t* vt)
{
    const int WN = Hd * Hd;
    const int y = blockIdx.y;
    GArgs g;
    g.lda = Hd; g.ldb = Hd; g.ldc = Hd; g.K = Hd; g.alpha = 1.f;
    g.n0 = blockIdx.x * 64; g.rs = nullptr;
    g.tr_ld = 1; g.tr_rows = 1; g.tr_col0 = 0;
    bool om2 = false;
    if (y < 128) {
        g.A = im; g.B = w + 0 * WN; g.bias = i2t_bq; g.C = qi; g.m0 = y * 128;
    } else if (y < 256) {
        g.A = im; g.B = w + 5 * WN; g.bias = t2i_bk; g.C = ki; g.m0 = (y - 128) * 128;
    } else if (y < 384) {
        g.A = im; g.B = w + 6 * WN; g.bias = t2i_bv; g.C = vi; g.m0 = (y - 256) * 128;
        g.tr_ld = SQI; g.tr_rows = SQI; g.tr_col0 = blockIdx.x; om2 = true;
    } else if (y < 448) {
        g.A = tx; g.B = w + 4 * WN; g.bias = t2i_bq; g.C = qt; g.m0 = (y - 384) * 128;
    } else if (y < 512) {
        g.A = tx; g.B = w + 1 * WN; g.bias = i2t_bk; g.C = kt; g.m0 = (y - 448) * 128;
    } else {
        g.A = tx; g.B = w + 2 * WN; g.bias = i2t_bv; g.C = vt; g.m0 = (y - 512) * 128;
        g.tr_ld = SQT; g.tr_rows = SQT; g.tr_col0 = blockIdx.x; om2 = true;
    }
    if (om2) gemm_mma<2, true>(g); else gemm_mma<1, true>(g);
}

__global__ void k_avg_all(const uint32_t* S0, const uint32_t* S1, const float* rsum,
                          float* A0, float* A1)
{
    const int b = blockIdx.y, t = threadIdx.x;
    int q = blockIdx.x;
    const uint32_t* W; const float* rs; float* A; int Sq, Skv;
    if (q < SQI) { W = S0; rs = rsum;            A = A0; Sq = SQI; Skv = SQT; }
    else { q -= SQI; W = S1; rs = rsum + NZ*SQI; A = A1; Sq = SQT; Skv = SQI; }
    const size_t hstride = (size_t)Sq * Skv;
    float inv[4];
#pragma unroll
    for (int h = 0; h < 4; h++) inv[h] = 0.25f / rs[(size_t)(b * 4 + h) * Sq + q];
    const uint32_t* w0 = W + ((size_t)(b * 4) * Sq + q) * (size_t)Skv;
    float* Ar = A + ((size_t)b * Sq + q) * (size_t)Skv;
    for (int k = t; k < Skv; k += 256) {
        float a = 0.f;
#pragma unroll
        for (int h = 0; h < 4; h++)
            a += unpack_f32(w0[(size_t)h * hstride + k]) * inv[h];
        Ar[k] = a;
    }
}

__global__ void __launch_bounds__(256) k_projout_all(
    const uint32_t* ai, const uint32_t* at, const uint32_t* w,
    const float* i2t_bo, const float* t2i_bo, float* oi, float* ot)
{
    const int WN = Hd * Hd;
    const int y = blockIdx.y;
    GArgs g;
    g.lda = Hd; g.ldb = Hd; g.ldc = Hd; g.K = Hd; g.alpha = 1.f;
    g.n0 = blockIdx.x * 64; g.rs = nullptr;
    g.tr_ld = 1; g.tr_rows = 1; g.tr_col0 = 0;
    if (y < 128) { g.A = ai; g.B = w + 3 * WN; g.bias = i2t_bo; g.C = oi; g.m0 = y * 128; }
    else         { g.A = at; g.B = w + 7 * WN; g.bias = t2i_bo; g.C = ot; g.m0 = (y - 128) * 128; }
    gemm_mma<0, true>(g);
}

__global__ void k_reluln_all(const float* oi, const float* ot,
                             const float* g0, const float* b0f,
                             const float* g1, const float* b1f,
                             float* out0, float* out1)
{
    __shared__ float s1[256], s2[256];
    int row = blockIdx.x;
    const int t = threadIdx.x;
    const float* O; const float* gamma; const float* beta; float* out;
    if (row < RI) { O = oi; gamma = g0; beta = b0f; out = out0; }
    else { row -= RI; O = ot; gamma = g1; beta = b1f; out = out1; }
    float x = O[(size_t)row * Hd + t];
    x = fmaxf(x, 0.f);
    s1[t] = x; s2[t] = x * x;
    __syncthreads();
    for (int s = 128; s > 0; s >>= 1) {
        if (t < s) { s1[t] += s1[t + s]; s2[t] += s2[t + s]; }
        __syncthreads();
    }
    const float mean = s1[0] * (1.f / Hd);
    const float var = s2[0] * (1.f / Hd) - mean * mean;
    const float rstd = rsqrtf(var + 1e-5f);
    out[(size_t)row * Hd + t] = (x - mean) * rstd * gamma[t] + beta[t];
}

// ---------------- launch ----------------
extern "C" void kernel_launch(void* const* d_in, const int* in_sizes, int n_in,
                              void* d_out, int out_size) {
    const float* image  = (const float*)d_in[0];
    const float* text   = (const float*)d_in[1];
    const float* i2t_wq = (const float*)d_in[2];
    const float* i2t_bq = (const float*)d_in[3];
    const float* i2t_wk = (const float*)d_in[4];
    const float* i2t_bk = (const float*)d_in[5];
    const float* i2t_wv = (const float*)d_in[6];
    const float* i2t_bv = (const float*)d_in[7];
    const float* i2t_wo = (const float*)d_in[8];
    const float* i2t_bo = (const float*)d_in[9];
    const float* i2t_g  = (const float*)d_in[10];
    const float* i2t_be = (const float*)d_in[11];
    const float* t2i_wq = (const float*)d_in[12];
    const float* t2i_bq = (const float*)d_in[13];
    const float* t2i_wk = (const float*)d_in[14];
    const float* t2i_bk = (const float*)d_in[15];
    const float* t2i_wv = (const float*)d_in[16];
    const float* t2i_bv = (const float*)d_in[17];
    const float* t2i_wo = (const float*)d_in[18];
    const float* t2i_bo = (const float*)d_in[19];
    const float* t2i_g  = (const float*)d_in[20];
    const float* t2i_be = (const float*)d_in[21];

    float* out = (float*)d_out;
    float* out_i2t_feat = out;
    float* out_t2i_feat = out + (size_t)RI * Hd;
    float* out_i2t_A    = out_t2i_feat + (size_t)RT * Hd;
    float* out_t2i_A    = out_i2t_A + (size_t)BAT * SQI * SQT;

    float *im, *tx, *w, *qi, *ki, *vi, *qt, *kt, *vt, *ai, *at, *oi, *ot;
    float *S0, *S1, *rsum;
    cudaGetSymbolAddress((void**)&im, g_im);
    cudaGetSymbolAddress((void**)&tx, g_tx);
    cudaGetSymbolAddress((void**)&w,  g_w);
    cudaGetSymbolAddress((void**)&qi, g_qi);
    cudaGetSymbolAddress((void**)&ki, g_ki);
    cudaGetSymbolAddress((void**)&vi, g_vi);
    cudaGetSymbolAddress((void**)&qt, g_qt);
    cudaGetSymbolAddress((void**)&kt, g_kt);
    cudaGetSymbolAddress((void**)&vt, g_vt);
    cudaGetSymbolAddress((void**)&ai, g_ai);
    cudaGetSymbolAddress((void**)&at, g_at);
    cudaGetSymbolAddress((void**)&oi, g_oi);
    cudaGetSymbolAddress((void**)&ot, g_ot);
    cudaGetSymbolAddress((void**)&S0, g_S0);
    cudaGetSymbolAddress((void**)&S1, g_S1);
    cudaGetSymbolAddress((void**)&rsum, g_rsum);

    cudaFuncSetAttribute(k_proj_all,    cudaFuncAttributeMaxDynamicSharedMemorySize, SMEM_GEMM);
    cudaFuncSetAttribute(k_attn_all,    cudaFuncAttributeMaxDynamicSharedMemorySize, SMEM_ATT);
    cudaFuncSetAttribute(k_projout_all, cudaFuncAttributeMaxDynamicSharedMemorySize, SMEM_GEMM);

    const dim3 blk(256);
    const int NPACK = RI * Hd + RT * Hd + 8 * Hd * Hd;

    k_pack_all<<<(NPACK + 255) / 256, blk>>>(
        image, text, i2t_wq, i2t_wk, i2t_wv, i2t_wo, t2i_wq, t2i_wk, t2i_wv, t2i_wo,
        (uint32_t*)im, (uint32_t*)tx, (uint32_t*)w);

    k_proj_all<<<dim3(4, 576), blk, SMEM_GEMM>>>(
        (uint32_t*)im, (uint32_t*)tx, (uint32_t*)w,
        i2t_bq, i2t_bk, i2t_bv, t2i_bq, t2i_bk, t2i_bv,
        (uint32_t*)qi, (uint32_t*)ki, (uint32_t*)vi,
        (uint32_t*)qt, (uint32_t*)kt, (uint32_t*)vt);

    // fused scores+exp+rowsum+PV: t2i occupies x<8 (longer blocks first), i2t x 8..23
    k_attn_all<<<dim3(24, 32), blk, SMEM_ATT>>>(
        (uint32_t*)qi, (uint32_t*)kt, (uint32_t*)qt, (uint32_t*)ki,
        (uint32_t*)vt, (uint32_t*)vi,
        (uint32_t*)S0, (uint32_t*)S1, rsum, (uint32_t*)ai, (uint32_t*)at);

    k_avg_all<<<dim3(SQI + SQT, BAT), blk>>>(
        (uint32_t*)S0, (uint32_t*)S1, rsum, out_i2t_A, out_t2i_A);

    k_projout_all<<<dim3(4, 192), blk, SMEM_GEMM>>>(
        (uint32_t*)ai, (uint32_t*)at, (uint32_t*)w, i2t_bo, t2i_bo, oi, ot);

    k_reluln_all<<<RI + RT, blk>>>(oi, ot, i2t_g, i2t_be, t2i_g, t2i_be,
                                   out_i2t_feat, out_t2i_feat);
}

// round 16
// speedup vs baseline: 1.0096x; 1.0096x over previous
#include <cuda_runtime.h>
#include <cuda_bf16.h>
#include <cstdint>
#include <math.h>

// ---------------- problem constants ----------------
#define Hd   256
#define NHd  4
#define HDd  64
#define BAT  8
#define SQI  2048
#define SQT  1024
#define RI   (BAT*SQI)
#define RT   (BAT*SQT)
#define NZ   (BAT*NHd)       // 32

// ---------------- scratch ----------------
__device__ float g_im[(size_t)RI*Hd];
__device__ float g_tx[(size_t)RT*Hd];
__device__ float g_w[8*(size_t)Hd*Hd];
__device__ float g_qi[(size_t)RI*Hd];
__device__ float g_ki[(size_t)RI*Hd];
__device__ float g_vi[(size_t)RI*Hd];   // packed, TRANSPOSED [z][64][SQI]
__device__ float g_qt[(size_t)RT*Hd];
__device__ float g_kt[(size_t)RT*Hd];
__device__ float g_vt[(size_t)RT*Hd];   // packed, TRANSPOSED [z][64][SQT]
__device__ float g_ai[(size_t)RI*Hd];
__device__ float g_at[(size_t)RT*Hd];
__device__ float g_S0[(size_t)NZ*SQI*SQT]; // i2t packed w (for A output)
__device__ float g_S1[(size_t)NZ*SQT*SQI]; // t2i packed w
__device__ float g_rsum[NZ*SQI + NZ*SQT];

// ================= helpers =================
__device__ __forceinline__ uint32_t smem_to_u32(const void* p) {
    uint32_t a;
    asm("{ .reg .u64 t; cvta.to.shared.u64 t, %1; cvt.u32.u64 %0, t; }" : "=r"(a) : "l"(p));
    return a;
}
__device__ __forceinline__ void ldm_x4(uint32_t r[4], uint32_t addr) {
    asm volatile("ldmatrix.sync.aligned.m8n8.x4.shared.b16 {%0,%1,%2,%3}, [%4];"
        : "=r"(r[0]), "=r"(r[1]), "=r"(r[2]), "=r"(r[3]) : "r"(addr));
}
__device__ __forceinline__ void mma_bf16(float c[4], const uint32_t a[4],
                                         uint32_t b0, uint32_t b1) {
    asm volatile(
        "mma.sync.aligned.m16n8k16.row.col.f32.bf16.bf16.f32 "
        "{%0,%1,%2,%3}, {%4,%5,%6,%7}, {%8,%9}, {%0,%1,%2,%3};"
        : "+f"(c[0]), "+f"(c[1]), "+f"(c[2]), "+f"(c[3])
        : "r"(a[0]), "r"(a[1]), "r"(a[2]), "r"(a[3]), "r"(b0), "r"(b1));
}
__device__ __forceinline__ uint32_t pack_f32(float x) {
    __nv_bfloat16 hb = __float2bfloat16(x);
    float hf = __bfloat162float(hb);
    __nv_bfloat16 lb = __float2bfloat16(x - hf);
    return ((uint32_t)__bfloat16_as_ushort(hb) << 16) | (uint32_t)__bfloat16_as_ushort(lb);
}
__device__ __forceinline__ float unpack_f32(uint32_t u) {
    return __bfloat162float(__ushort_as_bfloat16((unsigned short)(u >> 16)))
         + __bfloat162float(__ushort_as_bfloat16((unsigned short)(u & 0xffff)));
}
__device__ __forceinline__ void split2(float a, float b, uint32_t& h, uint32_t& l) {
    __nv_bfloat16 ah = __float2bfloat16(a), bh = __float2bfloat16(b);
    __nv_bfloat16 al = __float2bfloat16(a - __bfloat162float(ah));
    __nv_bfloat16 bl = __float2bfloat16(b - __bfloat162float(bh));
    h = ((uint32_t)__bfloat16_as_ushort(bh) << 16) | (uint32_t)__bfloat16_as_ushort(ah);
    l = ((uint32_t)__bfloat16_as_ushort(bl) << 16) | (uint32_t)__bfloat16_as_ushort(al);
}
__device__ __forceinline__ void sts8(uint16_t* hi, uint16_t* lo, int idx, uint4 a, uint4 b) {
    uint4 H, L;
    H.x = __byte_perm(a.x, a.y, 0x7632); H.y = __byte_perm(a.z, a.w, 0x7632);
    H.z = __byte_perm(b.x, b.y, 0x7632); H.w = __byte_perm(b.z, b.w, 0x7632);
    L.x = __byte_perm(a.x, a.y, 0x5410); L.y = __byte_perm(a.z, a.w, 0x5410);
    L.z = __byte_perm(b.x, b.y, 0x5410); L.w = __byte_perm(b.z, b.w, 0x5410);
    *(uint4*)(hi + idx) = H;
    *(uint4*)(lo + idx) = L;
}
__device__ __forceinline__ void sts4p(uint16_t* hi, uint16_t* lo, int idx, uint4 a) {
    uint2 H, L;
    H.x = __byte_perm(a.x, a.y, 0x7632); H.y = __byte_perm(a.z, a.w, 0x7632);
    L.x = __byte_perm(a.x, a.y, 0x5410); L.y = __byte_perm(a.z, a.w, 0x5410);
    *(uint2*)(hi + idx) = H;
    *(uint2*)(lo + idx) = L;
}

// ---------------- GEMM smem layout (QKV projections) ----------------
#define RSTR 56
#define OFF_AL 14336
#define OFF_BH 28672
#define OFF_BL 35840
#define STG_BYTES 43008
#define SMEM_GEMM (2*STG_BYTES)

struct GArgs {
    const uint32_t* A; int lda;
    const uint32_t* B; int ldb;
    const float* bias;
    void* C; int ldc;
    int K; float alpha;
    int m0, n0;
    int tr_ld, tr_rows, tr_col0;
};

// OMODE: 1 packed row-major, 2 packed transposed
template <int OMODE, bool BIAS>
__device__ void gemm_mma(GArgs g) {
    extern __shared__ char smem[];
    const uint32_t sbase = smem_to_u32(smem);
    const int tid = threadIdx.x;
    const int lane = tid & 31, wid = tid >> 5;
    const int warpM = wid >> 1, warpN = wid & 1;

    float c[2][4][4];
#pragma unroll
    for (int i = 0; i < 2; i++)
#pragma unroll
        for (int j = 0; j < 4; j++)
#pragma unroll
            for (int q = 0; q < 4; q++) c[i][j][q] = 0.f;

    const int S = g.K >> 5;
    const int arow = tid >> 1, ak0 = (tid & 1) * 16;
    const int brow = tid >> 2, bk0 = (tid & 3) * 8;
    uint4 areg[4], breg[2];

#define LOADR(s) do { \
        const uint32_t* Ap = g.A + (size_t)(g.m0 + arow) * g.lda + (s) * 32 + ak0; \
        _Pragma("unroll") for (int j = 0; j < 4; j++) areg[j] = *(const uint4*)(Ap + j * 4); \
        const uint32_t* Bp = g.B + (size_t)(g.n0 + brow) * g.ldb + (s) * 32 + bk0; \
        _Pragma("unroll") for (int j = 0; j < 2; j++) breg[j] = *(const uint4*)(Bp + j * 4); \
    } while (0)

#define STS(buf) do { \
        char* p = smem + (buf) * STG_BYTES; \
        uint16_t* Ah = (uint16_t*)p;               uint16_t* Al = (uint16_t*)(p + OFF_AL); \
        uint16_t* Bh = (uint16_t*)(p + OFF_BH);    uint16_t* Bl = (uint16_t*)(p + OFF_BL); \
        sts8(Ah, Al, arow * RSTR + ak0,     areg[0], areg[1]); \
        sts8(Ah, Al, arow * RSTR + ak0 + 8, areg[2], areg[3]); \
        sts8(Bh, Bl, brow * RSTR + bk0,     breg[0], breg[1]); \
    } while (0)

    const int sel = lane >> 3, r8 = lane & 7;
    const int rloc = (sel & 1) * 8 + r8;
    const int cloc = (sel >> 1) * 8;

#define COMPUTE(buf) do { \
        uint32_t AhB = sbase + (buf) * STG_BYTES, AlB = AhB + OFF_AL; \
        uint32_t BhB = AhB + OFF_BH,              BlB = AhB + OFF_BL; \
        _Pragma("unroll") for (int kh = 0; kh < 2; kh++) { \
            uint32_t ah[2][4], al[2][4], bh[2][4], bl[2][4]; \
            _Pragma("unroll") for (int i = 0; i < 2; i++) { \
                uint32_t off = (uint32_t)(((warpM * 32 + i * 16 + rloc) * RSTR + kh * 16 + cloc) * 2); \
                ldm_x4(ah[i], AhB + off); ldm_x4(al[i], AlB + off); \
            } \
            _Pragma("unroll") for (int pp = 0; pp < 2; pp++) { \
                uint32_t off = (uint32_t)(((warpN * 32 + pp * 16 + rloc) * RSTR + kh * 16 + cloc) * 2); \
                ldm_x4(bh[pp], BhB + off); ldm_x4(bl[pp], BlB + off); \
            } \
            _Pragma("unroll") for (int i = 0; i < 2; i++) \
            _Pragma("unroll") for (int j = 0; j < 4; j++) { \
                const int pp = j >> 1, q = j & 1; \
                mma_bf16(c[i][j], ah[i], bh[pp][q], bh[pp][q + 2]); \
                mma_bf16(c[i][j], ah[i], bl[pp][q], bl[pp][q + 2]); \
                mma_bf16(c[i][j], al[i], bh[pp][q], bh[pp][q + 2]); \
            } \
        } \
    } while (0)

    LOADR(0); STS(0);
    __syncthreads();
    for (int s = 0; s < S; ++s) {
        if (s + 1 < S) LOADR(s + 1);
        COMPUTE(s & 1);
        if (s + 1 < S) STS((s + 1) & 1);
        __syncthreads();
    }

    const int gq = lane >> 2, tig = lane & 3;
#pragma unroll
    for (int i = 0; i < 2; i++) {
        const int r0 = g.m0 + warpM * 32 + i * 16 + gq;
#pragma unroll
        for (int j = 0; j < 4; j++) {
            const int nc = warpN * 32 + j * 8 + tig * 2;
            float v00 = c[i][j][0], v01 = c[i][j][1];
            float v10 = c[i][j][2], v11 = c[i][j][3];
            if (BIAS) {
                float b0 = g.bias[g.n0 + nc], b1 = g.bias[g.n0 + nc + 1];
                v00 += b0; v01 += b1; v10 += b0; v11 += b1;
            }
            if (OMODE == 1) {
                uint32_t* Cu = (uint32_t*)g.C;
                *(uint2*)(Cu + (size_t)r0 * g.ldc + g.n0 + nc)       = make_uint2(pack_f32(v00), pack_f32(v01));
                *(uint2*)(Cu + (size_t)(r0 + 8) * g.ldc + g.n0 + nc) = make_uint2(pack_f32(v10), pack_f32(v11));
            } else {
                uint32_t* Ct = (uint32_t*)g.C;
                const int bb0 = r0 / g.tr_rows, sr0 = r0 % g.tr_rows;
                const int bb1 = (r0 + 8) / g.tr_rows, sr1 = (r0 + 8) % g.tr_rows;
                const size_t base0 = (size_t)((bb0 * 4 + g.tr_col0) * 64 + nc) * g.tr_ld + sr0;
                const size_t base1 = (size_t)((bb1 * 4 + g.tr_col0) * 64 + nc) * g.tr_ld + sr1;
                Ct[base0]            = pack_f32(v00);
                Ct[base0 + g.tr_ld]  = pack_f32(v01);
                Ct[base1]            = pack_f32(v10);
                Ct[base1 + g.tr_ld]  = pack_f32(v11);
            }
        }
    }
#undef LOADR
#undef STS
#undef COMPUTE
}

// ---------------- fused attention kernel (unchanged from R15) ----------------
#define DSTR 72
#define ATT_SQH 0
#define ATT_SQL 18432
#define ATT_BUF 36864
#define ATT_KH  0
#define ATT_KL  9216
#define ATT_VH  18432
#define ATT_VL  27648
#define ATT_BUFSZ 36864
#define SMEM_ATT (ATT_BUF + 2*ATT_BUFSZ) // 110592

__global__ void __launch_bounds__(256) k_attn_all(
    const uint32_t* qi, const uint32_t* kt, const uint32_t* qt, const uint32_t* ki,
    const uint32_t* vt, const uint32_t* vi,
    uint32_t* S0, uint32_t* S1, float* rsum,
    uint32_t* ai, uint32_t* at)
{
    extern __shared__ char smem[];
    const uint32_t sb = smem_to_u32(smem);
    const int tid = threadIdx.x;
    const int lane = tid & 31, wid = tid >> 5;
    const int z = blockIdx.y, b = z >> 2, h = z & 3;
    const int x = blockIdx.x;

    const uint32_t *Q, *Km, *V;
    uint32_t *Sg, *O;
    float* rsg;
    int m0, Skv;
    if (x < 8) {          // t2i
        Q = qt + (size_t)b * SQT * Hd + h * HDd;
        Km = ki + (size_t)b * SQI * Hd + h * HDd;
        V = vi + (size_t)z * HDd * SQI;
        Sg = S1 + (size_t)z * SQT * SQI;
        O = at + (size_t)b * SQT * Hd + h * HDd;
        rsg = rsum + NZ * SQI + (size_t)z * SQT;
        m0 = x * 128; Skv = SQI;
    } else {              // i2t
        Q = qi + (size_t)b * SQI * Hd + h * HDd;
        Km = kt + (size_t)b * SQT * Hd + h * HDd;
        V = vt + (size_t)z * HDd * SQT;
        Sg = S0 + (size_t)z * SQI * SQT;
        O = ai + (size_t)b * SQI * Hd + h * HDd;
        rsg = rsum + (size_t)z * SQI;
        m0 = (x - 8) * 128; Skv = SQT;
    }
    const int nsteps = Skv >> 6;

    {
        const int qrow = tid >> 1, qoff = (tid & 1) * 32;
        const uint32_t* Qp = Q + (size_t)(m0 + qrow) * Hd + qoff;
        uint4 qv[8];
#pragma unroll
        for (int j = 0; j < 8; j++) qv[j] = *(const uint4*)(Qp + 4 * j);
        uint16_t* Qh = (uint16_t*)(smem + ATT_SQH);
        uint16_t* Ql = (uint16_t*)(smem + ATT_SQL);
#pragma unroll
        for (int j = 0; j < 4; j++)
            sts8(Qh, Ql, qrow * DSTR + qoff + 8 * j, qv[2 * j], qv[2 * j + 1]);
    }

    const int krow = tid >> 2, koff = (tid & 3) * 16;
    uint4 kreg[4], vreg[4];
#define ATT_LOAD(s) do { \
        const uint32_t* Kp = Km + (size_t)((s) * 64 + krow) * Hd + koff; \
        _Pragma("unroll") for (int j = 0; j < 4; j++) kreg[j] = *(const uint4*)(Kp + 4 * j); \
        const uint32_t* Vp = V + (size_t)krow * Skv + (s) * 64 + koff; \
        _Pragma("unroll") for (int j = 0; j < 4; j++) vreg[j] = *(const uint4*)(Vp + 4 * j); \
    } while (0)
#define ATT_STS(buf) do { \
        char* p = smem + ATT_BUF + (buf) * ATT_BUFSZ; \
        sts8((uint16_t*)(p + ATT_KH), (uint16_t*)(p + ATT_KL), krow * DSTR + koff,     kreg[0], kreg[1]); \
        sts8((uint16_t*)(p + ATT_KH), (uint16_t*)(p + ATT_KL), krow * DSTR + koff + 8, kreg[2], kreg[3]); \
        sts8((uint16_t*)(p + ATT_VH), (uint16_t*)(p + ATT_VL), krow * DSTR + koff,     vreg[0], vreg[1]); \
        sts8((uint16_t*)(p + ATT_VH), (uint16_t*)(p + ATT_VL), krow * DSTR + koff + 8, vreg[2], vreg[3]); \
    } while (0)

    const int sel = lane >> 3, r8 = lane & 7;
    const int rloc = (sel & 1) * 8 + r8;
    const int cloc = (sel >> 1) * 8;
    const int g = lane >> 2, qd = lane & 3;

    float o[8][4];
#pragma unroll
    for (int nt = 0; nt < 8; nt++)
#pragma unroll
        for (int e = 0; e < 4; e++) o[nt][e] = 0.f;
    float rs0 = 0.f, rs1 = 0.f;

    ATT_LOAD(0); ATT_STS(0);
    __syncthreads();

    for (int s = 0; s < nsteps; ++s) {
        const int buf = s & 1;
        if (s + 1 < nsteps) ATT_LOAD(s + 1);

        const uint32_t bufb = sb + ATT_BUF + buf * ATT_BUFSZ;
        float c[8][4];
#pragma unroll
        for (int nt = 0; nt < 8; nt++)
#pragma unroll
            for (int e = 0; e < 4; e++) c[nt][e] = 0.f;
#pragma unroll
        for (int kf = 0; kf < 4; kf++) {
            uint32_t qh[4], ql[4];
            const uint32_t qoffs = (uint32_t)(((16 * wid + rloc) * DSTR + kf * 16 + cloc) * 2);
            ldm_x4(qh, sb + ATT_SQH + qoffs);
            ldm_x4(ql, sb + ATT_SQL + qoffs);
#pragma unroll
            for (int pp = 0; pp < 4; pp++) {
                uint32_t kh[4], kl[4];
                const uint32_t koffs = (uint32_t)(((pp * 16 + rloc) * DSTR + kf * 16 + cloc) * 2);
                ldm_x4(kh, bufb + ATT_KH + koffs);
                ldm_x4(kl, bufb + ATT_KL + koffs);
#pragma unroll
                for (int q = 0; q < 2; q++) {
                    const int nt = pp * 2 + q;
                    mma_bf16(c[nt], qh, kh[q], kh[q + 2]);
                    mma_bf16(c[nt], qh, kl[q], kl[q + 2]);
                    mma_bf16(c[nt], ql, kh[q], kh[q + 2]);
                }
            }
        }
        const int kv0 = s * 64;
        const int row0 = m0 + 16 * wid + g;
        float w[8][4];
#pragma unroll
        for (int nt = 0; nt < 8; nt++) {
            w[nt][0] = __expf(2.0f * c[nt][0]);
            w[nt][1] = __expf(2.0f * c[nt][1]);
            w[nt][2] = __expf(2.0f * c[nt][2]);
            w[nt][3] = __expf(2.0f * c[nt][3]);
            rs0 += w[nt][0] + w[nt][1];
            rs1 += w[nt][2] + w[nt][3];
            const int col = kv0 + nt * 8 + 2 * qd;
            *(uint2*)&Sg[(size_t)row0 * Skv + col] =
                make_uint2(pack_f32(w[nt][0]), pack_f32(w[nt][1]));
            *(uint2*)&Sg[(size_t)(row0 + 8) * Skv + col] =
                make_uint2(pack_f32(w[nt][2]), pack_f32(w[nt][3]));
        }
        uint32_t ph[4][4], pl[4][4];
#pragma unroll
        for (int kf = 0; kf < 4; kf++) {
            const int n0 = 2 * kf, n1 = n0 + 1;
            split2(w[n0][0], w[n0][1], ph[kf][0], pl[kf][0]);
            split2(w[n0][2], w[n0][3], ph[kf][1], pl[kf][1]);
            split2(w[n1][0], w[n1][1], ph[kf][2], pl[kf][2]);
            split2(w[n1][2], w[n1][3], ph[kf][3], pl[kf][3]);
        }
#pragma unroll
        for (int kf = 0; kf < 4; kf++) {
#pragma unroll
            for (int pp = 0; pp < 4; pp++) {
                uint32_t vh[4], vl[4];
                const uint32_t voffs = (uint32_t)(((pp * 16 + rloc) * DSTR + kf * 16 + cloc) * 2);
                ldm_x4(vh, bufb + ATT_VH + voffs);
                ldm_x4(vl, bufb + ATT_VL + voffs);
#pragma unroll
                for (int q = 0; q < 2; q++) {
                    const int nt = pp * 2 + q;
                    mma_bf16(o[nt], ph[kf], vh[q], vh[q + 2]);
                    mma_bf16(o[nt], ph[kf], vl[q], vl[q + 2]);
                    mma_bf16(o[nt], pl[kf], vh[q], vh[q + 2]);
                }
            }
        }
        if (s + 1 < nsteps) ATT_STS((s + 1) & 1);
        __syncthreads();
    }

    rs0 += __shfl_xor_sync(0xffffffffu, rs0, 1);
    rs0 += __shfl_xor_sync(0xffffffffu, rs0, 2);
    rs1 += __shfl_xor_sync(0xffffffffu, rs1, 1);
    rs1 += __shfl_xor_sync(0xffffffffu, rs1, 2);
    const int row0 = m0 + 16 * wid + g;
    if (qd == 0) {
        rsg[row0] = rs0;
        rsg[row0 + 8] = rs1;
    }
    const float inv0 = 1.f / rs0, inv1 = 1.f / rs1;
#pragma unroll
    for (int nt = 0; nt < 8; nt++) {
        const int col = nt * 8 + 2 * qd;
        *(uint2*)&O[(size_t)row0 * Hd + col] =
            make_uint2(pack_f32(o[nt][0] * inv0), pack_f32(o[nt][1] * inv0));
        *(uint2*)&O[(size_t)(row0 + 8) * Hd + col] =
            make_uint2(pack_f32(o[nt][2] * inv1), pack_f32(o[nt][3] * inv1));
    }
#undef ATT_LOAD
#undef ATT_STS
}

// ---------------- fused O-proj + bias + relu + LayerNorm ----------------
// Block: 32 rows x 256 cols. 8 warps = 2(M) x 4(N). K=256, 8 stages of 32.
#define PRSTR 40
#define PLN_AH 0
#define PLN_AL 2560
#define PLN_BH 5120
#define PLN_BL 25600
#define PLN_STG 46080
#define SMEM_PLN (2*PLN_STG)   // 92160

__global__ void __launch_bounds__(256) k_projln_all(
    const uint32_t* ai, const uint32_t* at, const uint32_t* w,
    const float* i2t_bo, const float* t2i_bo,
    const float* g0, const float* be0, const float* g1, const float* be1,
    float* out0, float* out1)
{
    extern __shared__ char smem[];
    const uint32_t sbase = smem_to_u32(smem);
    const int WN = Hd * Hd;
    int x = blockIdx.x;
    const uint32_t *A, *W;
    const float *bias, *gamma, *beta;
    float* out;
    int m0;
    if (x < RI / 32) {
        A = ai; W = w + 3 * WN; bias = i2t_bo; gamma = g0; beta = be0;
        out = out0; m0 = x * 32;
    } else {
        x -= RI / 32;
        A = at; W = w + 7 * WN; bias = t2i_bo; gamma = g1; beta = be1;
        out = out1; m0 = x * 32;
    }

    const int tid = threadIdx.x, lane = tid & 31, wid = tid >> 5;
    const int warpM = wid >> 2, warpN = wid & 3;

    float c[8][4];
#pragma unroll
    for (int nt = 0; nt < 8; nt++)
#pragma unroll
        for (int e = 0; e < 4; e++) c[nt][e] = 0.f;

    const int ar = tid >> 3, ac = (tid & 7) * 4;   // A: row ar, words ac..+3
    uint4 areg, breg[8];

#define PLN_LOAD(s) do { \
        areg = *(const uint4*)(A + (size_t)(m0 + ar) * Hd + (s) * 32 + ac); \
        _Pragma("unroll") for (int j = 0; j < 8; j++) \
            breg[j] = *(const uint4*)(W + (size_t)(ar + 32 * j) * Hd + (s) * 32 + ac); \
    } while (0)
#define PLN_STS(buf) do { \
        char* p = smem + (buf) * PLN_STG; \
        sts4p((uint16_t*)(p + PLN_AH), (uint16_t*)(p + PLN_AL), ar * PRSTR + ac, areg); \
        _Pragma("unroll") for (int j = 0; j < 8; j++) \
            sts4p((uint16_t*)(p + PLN_BH), (uint16_t*)(p + PLN_BL), (ar + 32 * j) * PRSTR + ac, breg[j]); \
    } while (0)

    const int sel = lane >> 3, r8 = lane & 7;
    const int rloc = (sel & 1) * 8 + r8;
    const int cloc = (sel >> 1) * 8;

#define PLN_COMPUTE(buf) do { \
        uint32_t base = sbase + (buf) * PLN_STG; \
        _Pragma("unroll") for (int kh = 0; kh < 2; kh++) { \
            uint32_t ah[4], al[4]; \
            const uint32_t aoffs = (uint32_t)(((warpM * 16 + rloc) * PRSTR + kh * 16 + cloc) * 2); \
            ldm_x4(ah, base + PLN_AH + aoffs); \
            ldm_x4(al, base + PLN_AL + aoffs); \
            _Pragma("unroll") for (int pp = 0; pp < 4; pp++) { \
                uint32_t bh[4], bl[4]; \
                const uint32_t boffs = (uint32_t)(((warpN * 64 + pp * 16 + rloc) * PRSTR + kh * 16 + cloc) * 2); \
                ldm_x4(bh, base + PLN_BH + boffs); \
                ldm_x4(bl, base + PLN_BL + boffs); \
                _Pragma("unroll") for (int q = 0; q < 2; q++) { \
                    const int nt = pp * 2 + q; \
                    mma_bf16(c[nt], ah, bh[q], bh[q + 2]); \
                    mma_bf16(c[nt], ah, bl[q], bl[q + 2]); \
                    mma_bf16(c[nt], al, bh[q], bh[q + 2]); \
                } \
            } \
        } \
    } while (0)

    PLN_LOAD(0); PLN_STS(0);
    __syncthreads();
    for (int s = 0; s < 8; ++s) {
        if (s + 1 < 8) PLN_LOAD(s + 1);
        PLN_COMPUTE(s & 1);
        if (s + 1 < 8) PLN_STS((s + 1) & 1);
        __syncthreads();
    }

    // ---- bias + relu to smem LN buffer [32][256] fp32 ----
    float* lnb = (float*)smem;
    const int gq = lane >> 2, qd = lane & 3;
#pragma unroll
    for (int i = 0; i < 2; i++) {
        const int row = warpM * 16 + i * 8 + gq;
#pragma unroll
        for (int nt = 0; nt < 8; nt++) {
            const int col = warpN * 64 + nt * 8 + qd * 2;
            float v0 = fmaxf(c[nt][2 * i]     + bias[col],     0.f);
            float v1 = fmaxf(c[nt][2 * i + 1] + bias[col + 1], 0.f);
            *(float2*)&lnb[row * 256 + col] = make_float2(v0, v1);
        }
    }
    __syncthreads();

    // ---- LayerNorm: 8 threads per row ----
    const int r = tid >> 3, seg = tid & 7;
    float s1 = 0.f, s2 = 0.f;
#pragma unroll 8
    for (int j = 0; j < 32; j++) {
        float xx = lnb[r * 256 + seg * 32 + j];
        s1 += xx; s2 += xx * xx;
    }
#pragma unroll
    for (int msk = 1; msk < 8; msk <<= 1) {
        s1 += __shfl_xor_sync(0xffffffffu, s1, msk);
        s2 += __shfl_xor_sync(0xffffffffu, s2, msk);
    }
    const float mean = s1 * (1.f / Hd);
    const float var  = s2 * (1.f / Hd) - mean * mean;
    const float rstd = rsqrtf(var + 1e-5f);
    float* orow = out + (size_t)(m0 + r) * Hd;
#pragma unroll 8
    for (int j = 0; j < 32; j++) {
        const int col = seg * 32 + j;
        orow[col] = (lnb[r * 256 + col] - mean) * rstd * gamma[col] + beta[col];
    }
#undef PLN_LOAD
#undef PLN_STS
#undef PLN_COMPUTE
}

// ---------------- other kernels ----------------
__global__ void __launch_bounds__(256) k_pack_all(
    const float* im, const float* tx,
    const float* w0, const float* w1, const float* w2, const float* w3,
    const float* w4, const float* w5, const float* w6, const float* w7,
    uint32_t* dim, uint32_t* dtx, uint32_t* dw)
{
    const int NIM = RI * Hd, NTX = RT * Hd, NW = Hd * Hd;
    int i = blockIdx.x * 256 + threadIdx.x;
    if (i >= NIM + NTX + 8 * NW) return;
    if (i < NIM) { dim[i] = pack_f32(im[i]); return; }
    i -= NIM;
    if (i < NTX) { dtx[i] = pack_f32(tx[i]); return; }
    i -= NTX;
    const int wsel = i / NW, wi = i % NW;
    const float* src;
    switch (wsel) {
        case 0: src = w0; break; case 1: src = w1; break;
        case 2: src = w2; break; case 3: src = w3; break;
        case 4: src = w4; break; case 5: src = w5; break;
        case 6: src = w6; break; default: src = w7; break;
    }
    dw[(size_t)wsel * NW + wi] = pack_f32(src[wi]);
}

__global__ void __launch_bounds__(256) k_proj_all(
    const uint32_t* im, const uint32_t* tx, const uint32_t* w,
    const float* i2t_bq, const float* i2t_bk, const float* i2t_bv,
    const float* t2i_bq, const float* t2i_bk, const float* t2i_bv,
    uint32_t* qi, uint32_t* ki, uint32_t* vi,
    uint32_t* qt, uint32_t* kt, uint32_t* vt)
{
    const int WN = Hd * Hd;
    const int y = blockIdx.y;
    GArgs g;
    g.lda = Hd; g.ldb = Hd; g.ldc = Hd; g.K = Hd; g.alpha = 1.f;
    g.n0 = blockIdx.x * 64;
    g.tr_ld = 1; g.tr_rows = 1; g.tr_col0 = 0;
    bool om2 = false;
    if (y < 128) {
        g.A = im; g.B = w + 0 * WN; g.bias = i2t_bq; g.C = qi; g.m0 = y * 128;
    } else if (y < 256) {
        g.A = im; g.B = w + 5 * WN; g.bias = t2i_bk; g.C = ki; g.m0 = (y - 128) * 128;
    } else if (y < 384) {
        g.A = im; g.B = w + 6 * WN; g.bias = t2i_bv; g.C = vi; g.m0 = (y - 256) * 128;
        g.tr_ld = SQI; g.tr_rows = SQI; g.tr_col0 = blockIdx.x; om2 = true;
    } else if (y < 448) {
        g.A = tx; g.B = w + 4 * WN; g.bias = t2i_bq; g.C = qt; g.m0 = (y - 384) * 128;
    } else if (y < 512) {
        g.A = tx; g.B = w + 1 * WN; g.bias = i2t_bk; g.C = kt; g.m0 = (y - 448) * 128;
    } else {
        g.A = tx; g.B = w + 2 * WN; g.bias = i2t_bv; g.C = vt; g.m0 = (y - 512) * 128;
        g.tr_ld = SQT; g.tr_rows = SQT; g.tr_col0 = blockIdx.x; om2 = true;
    }
    if (om2) gemm_mma<2, true>(g); else gemm_mma<1, true>(g);
}

// head-averaged A, vectorized uint4/float4. grid (3072, 8)
__global__ void k_avg_all(const uint32_t* S0, const uint32_t* S1, const float* rsum,
                          float* A0, float* A1)
{
    const int b = blockIdx.y, t = threadIdx.x;
    int q = blockIdx.x;
    const uint32_t* W; const float* rs; float* A; int Sq, Skv;
    if (q < SQI) { W = S0; rs = rsum;            A = A0; Sq = SQI; Skv = SQT; }
    else { q -= SQI; W = S1; rs = rsum + NZ*SQI; A = A1; Sq = SQT; Skv = SQI; }
    const size_t hstride = (size_t)Sq * Skv;
    float inv[4];
#pragma unroll
    for (int h = 0; h < 4; h++) inv[h] = 0.25f / rs[(size_t)(b * 4 + h) * Sq + q];
    const uint32_t* w0 = W + ((size_t)(b * 4) * Sq + q) * (size_t)Skv;
    float* Ar = A + ((size_t)b * Sq + q) * (size_t)Skv;
    const int nvec = Skv >> 2;     // uint4 count per row
    for (int v = t; v < nvec; v += 256) {
        float4 acc = make_float4(0.f, 0.f, 0.f, 0.f);
#pragma unroll
        for (int h = 0; h < 4; h++) {
            uint4 u = *(const uint4*)(w0 + h * hstride + (size_t)v * 4);
            acc.x += unpack_f32(u.x) * inv[h];
            acc.y += unpack_f32(u.y) * inv[h];
            acc.z += unpack_f32(u.z) * inv[h];
            acc.w += unpack_f32(u.w) * inv[h];
        }
        *(float4*)(Ar + (size_t)v * 4) = acc;
    }
}

// ---------------- launch ----------------
extern "C" void kernel_launch(void* const* d_in, const int* in_sizes, int n_in,
                              void* d_out, int out_size) {
    const float* image  = (const float*)d_in[0];
    const float* text   = (const float*)d_in[1];
    const float* i2t_wq = (const float*)d_in[2];
    const float* i2t_bq = (const float*)d_in[3];
    const float* i2t_wk = (const float*)d_in[4];
    const float* i2t_bk = (const float*)d_in[5];
    const float* i2t_wv = (const float*)d_in[6];
    const float* i2t_bv = (const float*)d_in[7];
    const float* i2t_wo = (const float*)d_in[8];
    const float* i2t_bo = (const float*)d_in[9];
    const float* i2t_g  = (const float*)d_in[10];
    const float* i2t_be = (const float*)d_in[11];
    const float* t2i_wq = (const float*)d_in[12];
    const float* t2i_bq = (const float*)d_in[13];
    const float* t2i_wk = (const float*)d_in[14];
    const float* t2i_bk = (const float*)d_in[15];
    const float* t2i_wv = (const float*)d_in[16];
    const float* t2i_bv = (const float*)d_in[17];
    const float* t2i_wo = (const float*)d_in[18];
    const float* t2i_bo = (const float*)d_in[19];
    const float* t2i_g  = (const float*)d_in[20];
    const float* t2i_be = (const float*)d_in[21];

    float* out = (float*)d_out;
    float* out_i2t_feat = out;
    float* out_t2i_feat = out + (size_t)RI * Hd;
    float* out_i2t_A    = out_t2i_feat + (size_t)RT * Hd;
    float* out_t2i_A    = out_i2t_A + (size_t)BAT * SQI * SQT;

    float *im, *tx, *w, *qi, *ki, *vi, *qt, *kt, *vt, *ai, *at;
    float *S0, *S1, *rsum;
    cudaGetSymbolAddress((void**)&im, g_im);
    cudaGetSymbolAddress((void**)&tx, g_tx);
    cudaGetSymbolAddress((void**)&w,  g_w);
    cudaGetSymbolAddress((void**)&qi, g_qi);
    cudaGetSymbolAddress((void**)&ki, g_ki);
    cudaGetSymbolAddress((void**)&vi, g_vi);
    cudaGetSymbolAddress((void**)&qt, g_qt);
    cudaGetSymbolAddress((void**)&kt, g_kt);
    cudaGetSymbolAddress((void**)&vt, g_vt);
    cudaGetSymbolAddress((void**)&ai, g_ai);
    cudaGetSymbolAddress((void**)&at, g_at);
    cudaGetSymbolAddress((void**)&S0, g_S0);
    cudaGetSymbolAddress((void**)&S1, g_S1);
    cudaGetSymbolAddress((void**)&rsum, g_rsum);

    cudaFuncSetAttribute(k_proj_all,   cudaFuncAttributeMaxDynamicSharedMemorySize, SMEM_GEMM);
    cudaFuncSetAttribute(k_attn_all,   cudaFuncAttributeMaxDynamicSharedMemorySize, SMEM_ATT);
    cudaFuncSetAttribute(k_projln_all, cudaFuncAttributeMaxDynamicSharedMemorySize, SMEM_PLN);

    const dim3 blk(256);
    const int NPACK = RI * Hd + RT * Hd + 8 * Hd * Hd;

    k_pack_all<<<(NPACK + 255) / 256, blk>>>(
        image, text, i2t_wq, i2t_wk, i2t_wv, i2t_wo, t2i_wq, t2i_wk, t2i_wv, t2i_wo,
        (uint32_t*)im, (uint32_t*)tx, (uint32_t*)w);

    k_proj_all<<<dim3(4, 576), blk, SMEM_GEMM>>>(
        (uint32_t*)im, (uint32_t*)tx, (uint32_t*)w,
        i2t_bq, i2t_bk, i2t_bv, t2i_bq, t2i_bk, t2i_bv,
        (uint32_t*)qi, (uint32_t*)ki, (uint32_t*)vi,
        (uint32_t*)qt, (uint32_t*)kt, (uint32_t*)vt);

    k_attn_all<<<dim3(24, 32), blk, SMEM_ATT>>>(
        (uint32_t*)qi, (uint32_t*)kt, (uint32_t*)qt, (uint32_t*)ki,
        (uint32_t*)vt, (uint32_t*)vi,
        (uint32_t*)S0, (uint32_t*)S1, rsum, (uint32_t*)ai, (uint32_t*)at);

    k_avg_all<<<dim3(SQI + SQT, BAT), blk>>>(
        (uint32_t*)S0, (uint32_t*)S1, rsum, out_i2t_A, out_t2i_A);

    k_projln_all<<<RI / 32 + RT / 32, blk, SMEM_PLN>>>(
        (uint32_t*)ai, (uint32_t*)at, (uint32_t*)w,
        i2t_bo, t2i_bo, i2t_g, i2t_be, t2i_g, t2i_be,
        out_i2t_feat, out_t2i_feat);
}